// round 4
// baseline (speedup 1.0000x reference)
#include <cuda_runtime.h>
#include <cuda_fp16.h>
#include <math.h>

#define NPG 286        // real nodes per graph
#define NPGP 287       // + 1 dummy node for padded edges
#define EPG 4000       // real edges per graph
#define EPGP 4096      // padded edges (512 threads * 8)
#define NGRAPH 8192
#define THREADS 512
#define EPT 8          // edges per thread

__global__ __launch_bounds__(THREADS)
void gnn_kernel(const float* __restrict__ feat,
                const int*   __restrict__ src,
                const int*   __restrict__ dst,
                const float* __restrict__ W1, const float* __restrict__ b1,
                const float* __restrict__ W2, const float* __restrict__ b2,
                const float* __restrict__ Wfc, const float* __restrict__ bfc,
                float* __restrict__ out)
{
    __shared__ unsigned int s_csr[EPGP];          // low16 = src, high16 = dst, sorted by dst
    __shared__ unsigned int s_fxy[NPGP + 1];      // half2 (x, y), pre-scaled
    __shared__ float        s_fz [NPGP + 1];      // z fp32, pre-scaled
    __shared__ float s_ax[NPGP + 1], s_ay[NPGP + 1], s_az[NPGP + 1];
    __shared__ int   s_degin [NPGP + 1];
    __shared__ int   s_degout[NPGP + 1];
    __shared__ int   s_cur   [NPGP + 1];
    __shared__ float s_nin [NPGP + 1];
    __shared__ float s_nout[NPGP + 1];
    __shared__ int   s_wsum[16];
    __shared__ float s_red[16];

    const int g    = blockIdx.x;
    const int tid  = threadIdx.x;
    const int lane = tid & 31;
    const int warp = tid >> 5;
    const int base = g * NPG;
    const int* __restrict__ srcp = src + (long long)g * EPG;
    const int* __restrict__ dstp = dst + (long long)g * EPG;

    // ---- init counters ----
    if (tid < NPGP) { s_degin[tid] = 0; s_degout[tid] = 0; }
    __syncthreads();

    // ---- load 8 edges into registers (vectorized, coalesced), count degrees ----
    unsigned er[EPT];
    if (tid < EPG / EPT) {                 // threads 0..499: real edges
        const int4* sp = (const int4*)(srcp) + tid * 2;
        const int4* dp = (const int4*)(dstp) + tid * 2;
        int4 s0 = sp[0], s1 = sp[1];
        int4 d0 = dp[0], d1 = dp[1];
        int ss[EPT] = { s0.x, s0.y, s0.z, s0.w, s1.x, s1.y, s1.z, s1.w };
        int dd[EPT] = { d0.x, d0.y, d0.z, d0.w, d1.x, d1.y, d1.z, d1.w };
        #pragma unroll
        for (int i = 0; i < EPT; i++) {
            int s = ss[i] - base;
            int d = dd[i] - base;
            er[i] = (unsigned)s | ((unsigned)d << 16);
            atomicAdd(&s_degout[s], 1);
            atomicAdd(&s_degin[d], 1);
        }
    } else {                               // threads 500..511: dummy edges -> node 286
        #pragma unroll
        for (int i = 0; i < EPT; i++) {
            er[i] = (unsigned)NPG | ((unsigned)NPG << 16);
            atomicAdd(&s_degout[NPG], 1);
            atomicAdd(&s_degin[NPG], 1);
        }
    }
    __syncthreads();

    // ---- warp-shfl scan of deg_in -> exclusive offsets (cursors) + norms ----
    int degv = (tid < NPGP) ? s_degin[tid] : 0;
    int v = degv;
    #pragma unroll
    for (int o = 1; o < 32; o <<= 1) {
        int n = __shfl_up_sync(0xFFFFFFFFu, v, o);
        if (lane >= o) v += n;
    }
    if (lane == 31) s_wsum[warp] = v;
    __syncthreads();
    if (warp == 0 && lane < 16) {
        int w = s_wsum[lane];
        #pragma unroll
        for (int o = 1; o < 16; o <<= 1) {
            int n = __shfl_up_sync(0xFFFFu, w, o);
            if (lane >= o) w += n;
        }
        s_wsum[lane] = w;
    }
    __syncthreads();
    if (tid < NPGP) {
        s_cur[tid]  = v + (warp ? s_wsum[warp - 1] : 0) - degv;  // exclusive offset
        s_nin[tid]  = rsqrtf(fmaxf((float)degv, 1.0f));
        s_nout[tid] = rsqrtf(fmaxf((float)s_degout[tid], 1.0f));
    }
    __syncthreads();

    // ---- counting-sort scatter: edges (from regs) sorted by dst ----
    #pragma unroll
    for (int i = 0; i < EPT; i++) {
        int d = (int)(er[i] >> 16);
        int pos = atomicAdd(&s_cur[d], 1);
        s_csr[pos] = er[i];
    }

    // ---- load features, scale by norm_out, pack (x,y)->half2, z fp32 ----
    if (tid < NPGP) {
        if (tid < NPG) {
            const float* fp = feat + (long long)(base + tid) * 3;
            float no = s_nout[tid];
            __half2 h = __floats2half2_rn(fp[0] * no, fp[1] * no);
            s_fxy[tid] = *(unsigned*)&h;
            s_fz[tid]  = fp[2] * no;
        } else {
            s_fxy[tid] = 0u;
            s_fz[tid]  = 0.f;
        }
        s_ax[tid] = 0.f; s_ay[tid] = 0.f; s_az[tid] = 0.f;
    }
    __syncthreads();

    // ---- layer 1 gather: load this thread's CSR chunk into regs (keep for L2) ----
    unsigned ec[EPT];
    {
        const uint4* cp = (const uint4*)s_csr + tid * 2;
        uint4 c0 = cp[0], c1 = cp[1];
        ec[0] = c0.x; ec[1] = c0.y; ec[2] = c0.z; ec[3] = c0.w;
        ec[4] = c1.x; ec[5] = c1.y; ec[6] = c1.z; ec[7] = c1.w;
    }
    {
        int cur = (int)(ec[0] >> 16);
        int s   = (int)(ec[0] & 0xFFFFu);
        unsigned pxy = s_fxy[s];
        float2 f2 = __half22float2(*(__half2*)&pxy);
        float ax = f2.x, ay = f2.y, az = s_fz[s];
        #pragma unroll
        for (int i = 1; i < EPT; i++) {
            int d = (int)(ec[i] >> 16);
            s = (int)(ec[i] & 0xFFFFu);
            pxy = s_fxy[s];
            f2 = __half22float2(*(__half2*)&pxy);
            float vz = s_fz[s];
            if (d != cur) {
                atomicAdd(&s_ax[cur], ax);
                atomicAdd(&s_ay[cur], ay);
                atomicAdd(&s_az[cur], az);
                cur = d; ax = f2.x; ay = f2.y; az = vz;
            } else {
                ax += f2.x; ay += f2.y; az += vz;
            }
        }
        atomicAdd(&s_ax[cur], ax);
        atomicAdd(&s_ay[cur], ay);
        atomicAdd(&s_az[cur], az);
    }
    __syncthreads();

    // ---- layer 1 node transform ----
    if (tid < NPGP) {
        if (tid < NPG) {
            float ni = s_nin[tid];
            float ax = s_ax[tid] * ni, ay = s_ay[tid] * ni, az = s_az[tid] * ni;
            float o0 = fmaxf(fmaf(ax, __ldg(W1+0), fmaf(ay, __ldg(W1+3), fmaf(az, __ldg(W1+6), __ldg(b1+0)))), 0.f);
            float o1 = fmaxf(fmaf(ax, __ldg(W1+1), fmaf(ay, __ldg(W1+4), fmaf(az, __ldg(W1+7), __ldg(b1+1)))), 0.f);
            float o2 = fmaxf(fmaf(ax, __ldg(W1+2), fmaf(ay, __ldg(W1+5), fmaf(az, __ldg(W1+8), __ldg(b1+2)))), 0.f);
            float no = s_nout[tid];
            __half2 h = __floats2half2_rn(o0 * no, o1 * no);
            s_fxy[tid] = *(unsigned*)&h;
            s_fz[tid]  = o2 * no;
        } else {
            s_fxy[tid] = 0u;
            s_fz[tid]  = 0.f;
        }
        s_ax[tid] = 0.f; s_ay[tid] = 0.f; s_az[tid] = 0.f;
    }
    __syncthreads();

    // ---- layer 2 gather: reuse CSR chunk from registers ----
    {
        int cur = (int)(ec[0] >> 16);
        int s   = (int)(ec[0] & 0xFFFFu);
        unsigned pxy = s_fxy[s];
        float2 f2 = __half22float2(*(__half2*)&pxy);
        float ax = f2.x, ay = f2.y, az = s_fz[s];
        #pragma unroll
        for (int i = 1; i < EPT; i++) {
            int d = (int)(ec[i] >> 16);
            s = (int)(ec[i] & 0xFFFFu);
            pxy = s_fxy[s];
            f2 = __half22float2(*(__half2*)&pxy);
            float vz = s_fz[s];
            if (d != cur) {
                atomicAdd(&s_ax[cur], ax);
                atomicAdd(&s_ay[cur], ay);
                atomicAdd(&s_az[cur], az);
                cur = d; ax = f2.x; ay = f2.y; az = vz;
            } else {
                ax += f2.x; ay += f2.y; az += vz;
            }
        }
        atomicAdd(&s_ax[cur], ax);
        atomicAdd(&s_ay[cur], ay);
        atomicAdd(&s_az[cur], az);
    }
    __syncthreads();

    // ---- layer 2 node transform: raw outputs back into s_a* ----
    if (tid < NPG) {
        float ni = s_nin[tid];
        float ax = s_ax[tid] * ni, ay = s_ay[tid] * ni, az = s_az[tid] * ni;
        float o0 = fmaxf(fmaf(ax, __ldg(W2+0), fmaf(ay, __ldg(W2+3), fmaf(az, __ldg(W2+6), __ldg(b2+0)))), 0.f);
        float o1 = fmaxf(fmaf(ax, __ldg(W2+1), fmaf(ay, __ldg(W2+4), fmaf(az, __ldg(W2+7), __ldg(b2+1)))), 0.f);
        float o2 = fmaxf(fmaf(ax, __ldg(W2+2), fmaf(ay, __ldg(W2+5), fmaf(az, __ldg(W2+8), __ldg(b2+2)))), 0.f);
        s_ax[tid] = o0; s_ay[tid] = o1; s_az[tid] = o2;
    }
    __syncthreads();

    // ---- FC: out[g] = sigmoid( sum_k x2_flat[k] * Wfc[k] + bfc ) ----
    float acc = 0.f;
    for (int k = tid; k < NPG * 3; k += THREADS) {
        int i = k / 3;
        int j = k - 3 * i;
        float val = (j == 0) ? s_ax[i] : (j == 1) ? s_ay[i] : s_az[i];
        acc += val * __ldg(Wfc + k);
    }
    #pragma unroll
    for (int o = 16; o > 0; o >>= 1) acc += __shfl_down_sync(0xFFFFFFFFu, acc, o);
    if (lane == 0) s_red[warp] = acc;
    __syncthreads();
    if (tid < 32) {
        float vv = (tid < (THREADS / 32)) ? s_red[tid] : 0.f;
        #pragma unroll
        for (int o = 8; o > 0; o >>= 1) vv += __shfl_down_sync(0xFFFFFFFFu, vv, o);
        if (tid == 0) {
            float z = vv + __ldg(bfc);
            out[g] = 1.0f / (1.0f + expf(-z));
        }
    }
}

extern "C" void kernel_launch(void* const* d_in, const int* in_sizes, int n_in,
                              void* d_out, int out_size)
{
    const float* feat = (const float*)d_in[0];
    const int*   src  = (const int*)  d_in[1];
    const int*   dst  = (const int*)  d_in[2];
    const float* W1   = (const float*)d_in[3];
    const float* b1   = (const float*)d_in[4];
    const float* W2   = (const float*)d_in[5];
    const float* b2   = (const float*)d_in[6];
    const float* Wfc  = (const float*)d_in[7];
    const float* bfc  = (const float*)d_in[8];

    int ngraph = out_size > 0 ? out_size : NGRAPH;
    gnn_kernel<<<ngraph, THREADS>>>(feat, src, dst, W1, b1, W2, b2, Wfc, bfc,
                                    (float*)d_out);
}

// round 7
// speedup vs baseline: 1.3273x; 1.3273x over previous
#include <cuda_runtime.h>
#include <cuda_fp16.h>
#include <math.h>

#define NPG 286        // nodes per graph
#define EPG 4000       // edges per graph
#define NGRAPH 8192
#define THREADS 512

__global__ __launch_bounds__(THREADS)
void gnn_kernel(const float* __restrict__ feat,
                const int*   __restrict__ src,
                const int*   __restrict__ dst,
                const float* __restrict__ W1, const float* __restrict__ b1,
                const float* __restrict__ W2, const float* __restrict__ b2,
                const float* __restrict__ Wfc, const float* __restrict__ bfc,
                float* __restrict__ out)
{
    __shared__ unsigned int s_edge[EPG];   // low16 = src, high16 = dst (load order)
    __shared__ unsigned int s_csr[EPG];    // low16 = src, high16 = dst, sorted by dst
    __shared__ unsigned int s_fxy[NPG];    // half2 (x, y), pre-scaled by norm_out
    __shared__ float        s_fz [NPG];    // z fp32, pre-scaled
    __shared__ __half2      s_axy[NPG];    // accumulator (x, y) as half2
    __shared__ float        s_az [NPG];    // accumulator z fp32
    __shared__ int   s_degin[NPG];
    __shared__ int   s_degout[NPG];
    __shared__ int   s_cur[NPG];           // scatter cursor
    __shared__ float s_nin[NPG];
    __shared__ float s_nout[NPG];
    __shared__ int   s_wsum[16];
    __shared__ float s_red[16];

    const int g    = blockIdx.x;
    const int tid  = threadIdx.x;
    const int lane = tid & 31;
    const int warp = tid >> 5;
    const int base = g * NPG;
    const int* __restrict__ srcp = src + (long long)g * EPG;
    const int* __restrict__ dstp = dst + (long long)g * EPG;

    // ---- init counters ----
    if (tid < NPG) { s_degin[tid] = 0; s_degout[tid] = 0; }
    __syncthreads();

    // ---- load edges (coalesced), count degrees ----
    for (int e = tid; e < EPG; e += THREADS) {
        int s = srcp[e] - base;
        int d = dstp[e] - base;
        s_edge[e] = (unsigned)s | ((unsigned)d << 16);
        atomicAdd(&s_degout[s], 1);
        atomicAdd(&s_degin[d], 1);
    }
    __syncthreads();

    // ---- warp-shfl scan of deg_in -> exclusive offsets (cursors) + norms ----
    int degv = (tid < NPG) ? s_degin[tid] : 0;
    int v = degv;
    #pragma unroll
    for (int o = 1; o < 32; o <<= 1) {
        int n = __shfl_up_sync(0xFFFFFFFFu, v, o);
        if (lane >= o) v += n;
    }
    if (lane == 31) s_wsum[warp] = v;
    __syncthreads();
    if (warp == 0 && lane < 16) {
        int w = s_wsum[lane];
        #pragma unroll
        for (int o = 1; o < 16; o <<= 1) {
            int n = __shfl_up_sync(0xFFFFu, w, o);
            if (lane >= o) w += n;
        }
        s_wsum[lane] = w;
    }
    __syncthreads();
    if (tid < NPG) {
        s_cur[tid]  = v + (warp ? s_wsum[warp - 1] : 0) - degv;  // exclusive offset
        s_nin[tid]  = rsqrtf(fmaxf((float)degv, 1.0f));
        s_nout[tid] = rsqrtf(fmaxf((float)s_degout[tid], 1.0f));
    }
    __syncthreads();

    // ---- counting-sort scatter: edges sorted by dst ----
    for (int e = tid; e < EPG; e += THREADS) {
        unsigned sd = s_edge[e];
        int d = (int)(sd >> 16);
        int pos = atomicAdd(&s_cur[d], 1);
        s_csr[pos] = sd;
    }

    // ---- load features (node-parallel), scale by norm_out, pack (x,y)->half2 ----
    if (tid < NPG) {
        const float* fp = feat + (long long)(base + tid) * 3;
        float no = s_nout[tid];
        __half2 h = __floats2half2_rn(fp[0] * no, fp[1] * no);
        s_fxy[tid] = *(unsigned*)&h;
        s_fz[tid]  = fp[2] * no;
        s_axy[tid] = __floats2half2_rn(0.f, 0.f);
        s_az[tid]  = 0.f;
    }
    __syncthreads();

    // ===================== layer 1: edge-parallel segmented gather =====================
    {
        int e0 = (tid * EPG) / THREADS;
        int e1 = ((tid + 1) * EPG) / THREADS;
        unsigned sd = s_csr[e0];
        int cur = (int)(sd >> 16);
        int s   = (int)(sd & 0xFFFFu);
        unsigned pxy = s_fxy[s];
        float2 f2 = __half22float2(*(__half2*)&pxy);
        float ax = f2.x, ay = f2.y, az = s_fz[s];
        for (int e = e0 + 1; e < e1; e++) {
            sd = s_csr[e];
            int d = (int)(sd >> 16);
            s = (int)(sd & 0xFFFFu);
            pxy = s_fxy[s];
            f2 = __half22float2(*(__half2*)&pxy);
            float vz = s_fz[s];
            if (d != cur) {
                atomicAdd(&s_axy[cur], __floats2half2_rn(ax, ay));
                atomicAdd(&s_az[cur], az);
                cur = d; ax = f2.x; ay = f2.y; az = vz;
            } else {
                ax += f2.x; ay += f2.y; az += vz;
            }
        }
        atomicAdd(&s_axy[cur], __floats2half2_rn(ax, ay));
        atomicAdd(&s_az[cur], az);
    }
    __syncthreads();

    // ---- layer 1 node transform: norm_in, W1, relu, pre-scale next norm_out ----
    if (tid < NPG) {
        float ni = s_nin[tid];
        float2 a2 = __half22float2(s_axy[tid]);
        float ax = a2.x * ni, ay = a2.y * ni, az = s_az[tid] * ni;
        float o0 = fmaxf(fmaf(ax, __ldg(W1+0), fmaf(ay, __ldg(W1+3), fmaf(az, __ldg(W1+6), __ldg(b1+0)))), 0.f);
        float o1 = fmaxf(fmaf(ax, __ldg(W1+1), fmaf(ay, __ldg(W1+4), fmaf(az, __ldg(W1+7), __ldg(b1+1)))), 0.f);
        float o2 = fmaxf(fmaf(ax, __ldg(W1+2), fmaf(ay, __ldg(W1+5), fmaf(az, __ldg(W1+8), __ldg(b1+2)))), 0.f);
        float no = s_nout[tid];
        __half2 h = __floats2half2_rn(o0 * no, o1 * no);
        s_fxy[tid] = *(unsigned*)&h;
        s_fz[tid]  = o2 * no;
        s_axy[tid] = __floats2half2_rn(0.f, 0.f);
        s_az[tid]  = 0.f;
    }
    __syncthreads();

    // ===================== layer 2: edge-parallel segmented gather =====================
    {
        int e0 = (tid * EPG) / THREADS;
        int e1 = ((tid + 1) * EPG) / THREADS;
        unsigned sd = s_csr[e0];
        int cur = (int)(sd >> 16);
        int s   = (int)(sd & 0xFFFFu);
        unsigned pxy = s_fxy[s];
        float2 f2 = __half22float2(*(__half2*)&pxy);
        float ax = f2.x, ay = f2.y, az = s_fz[s];
        for (int e = e0 + 1; e < e1; e++) {
            sd = s_csr[e];
            int d = (int)(sd >> 16);
            s = (int)(sd & 0xFFFFu);
            pxy = s_fxy[s];
            f2 = __half22float2(*(__half2*)&pxy);
            float vz = s_fz[s];
            if (d != cur) {
                atomicAdd(&s_axy[cur], __floats2half2_rn(ax, ay));
                atomicAdd(&s_az[cur], az);
                cur = d; ax = f2.x; ay = f2.y; az = vz;
            } else {
                ax += f2.x; ay += f2.y; az += vz;
            }
        }
        atomicAdd(&s_axy[cur], __floats2half2_rn(ax, ay));
        atomicAdd(&s_az[cur], az);
    }
    __syncthreads();

    // ---- layer 2 node transform: raw outputs into s_fz-style scratch ----
    if (tid < NPG) {
        float ni = s_nin[tid];
        float2 a2 = __half22float2(s_axy[tid]);
        float ax = a2.x * ni, ay = a2.y * ni, az = s_az[tid] * ni;
        float o0 = fmaxf(fmaf(ax, __ldg(W2+0), fmaf(ay, __ldg(W2+3), fmaf(az, __ldg(W2+6), __ldg(b2+0)))), 0.f);
        float o1 = fmaxf(fmaf(ax, __ldg(W2+1), fmaf(ay, __ldg(W2+4), fmaf(az, __ldg(W2+7), __ldg(b2+1)))), 0.f);
        float o2 = fmaxf(fmaf(ax, __ldg(W2+2), fmaf(ay, __ldg(W2+5), fmaf(az, __ldg(W2+8), __ldg(b2+2)))), 0.f);
        // store raw fp32 outputs: reuse s_nin/s_nout/s_fz as x2 scratch (no longer needed)
        s_nin[tid]  = o0;
        s_nout[tid] = o1;
        s_fz[tid]   = o2;
    }
    __syncthreads();

    // ---- FC: out[g] = sigmoid( sum_k x2_flat[k] * Wfc[k] + bfc ) ----
    float acc = 0.f;
    for (int k = tid; k < NPG * 3; k += THREADS) {
        int i = k / 3;
        int j = k - 3 * i;
        float val = (j == 0) ? s_nin[i] : (j == 1) ? s_nout[i] : s_fz[i];
        acc += val * __ldg(Wfc + k);
    }
    #pragma unroll
    for (int o = 16; o > 0; o >>= 1) acc += __shfl_down_sync(0xFFFFFFFFu, acc, o);
    if (lane == 0) s_red[warp] = acc;
    __syncthreads();
    if (tid < 32) {
        float vv = (tid < (THREADS / 32)) ? s_red[tid] : 0.f;
        #pragma unroll
        for (int o = 8; o > 0; o >>= 1) vv += __shfl_down_sync(0xFFFFFFFFu, vv, o);
        if (tid == 0) {
            float z = vv + __ldg(bfc);
            out[g] = 1.0f / (1.0f + expf(-z));
        }
    }
}

extern "C" void kernel_launch(void* const* d_in, const int* in_sizes, int n_in,
                              void* d_out, int out_size)
{
    const float* feat = (const float*)d_in[0];
    const int*   src  = (const int*)  d_in[1];
    const int*   dst  = (const int*)  d_in[2];
    const float* W1   = (const float*)d_in[3];
    const float* b1   = (const float*)d_in[4];
    const float* W2   = (const float*)d_in[5];
    const float* b2   = (const float*)d_in[6];
    const float* Wfc  = (const float*)d_in[7];
    const float* bfc  = (const float*)d_in[8];

    int ngraph = out_size > 0 ? out_size : NGRAPH;
    gnn_kernel<<<ngraph, THREADS>>>(feat, src, dst, W1, b1, W2, b2, Wfc, bfc,
                                    (float*)d_out);
}